// round 9
// baseline (speedup 1.0000x reference)
#include <cuda_runtime.h>
#include <math_constants.h>

// Breadth_45896020525813 — fused GNN layer (round 9):
//   P = x @ (W1a - W1b)^T + b1 ; Q = x @ W1b^T     (node-level)
//   per edge: h = leaky(P[dst]+Q[src]); msg = h@W2^T ; max over edges per dst
//   out = tanh(max + b2), empty rows -> 0
//
// k_edge: block-per-node (128 thr). Thread owns ONE W2 row (64 regs) ->
// ~105 regs/thread -> 4-5 blocks/SM (16-20 warps, 2x round-8 occupancy).
// Halves of block process even/odd edges; h staged in smem (double-buffered,
// 1 syncthreads per edge-pair), consumed via broadcast LDS.128.

typedef unsigned long long ull;

#define NMAX 50000
#define EMAX 800000
#define SCAN_B 512

__device__ float g_P[NMAX * 64];   // P + b1, row-major [n][64]
__device__ float g_Q[NMAX * 64];
__device__ int   g_src_s[EMAX];    // src ids grouped by dst
__device__ int   g_deg[NMAX];      // zero at load; re-zeroed in k_scanC
__device__ int2  g_rowdeg[NMAX];   // {row start, degree}
__device__ int   g_cursor[NMAX];
__device__ int   g_part[128];

__device__ __forceinline__ ull pack2(float lo, float hi) {
    ull r;
    asm("mov.b64 %0, {%1, %2};" : "=l"(r) : "f"(lo), "f"(hi));
    return r;
}
__device__ __forceinline__ void unpack2(ull v, float& lo, float& hi) {
    asm("mov.b64 {%0, %1}, %2;" : "=f"(lo), "=f"(hi) : "l"(v));
}
__device__ __forceinline__ void fma2(ull& acc, ull a, ull b) {
    asm("fma.rn.f32x2 %0, %1, %2, %0;" : "+l"(acc) : "l"(a), "l"(b));
}
__device__ __forceinline__ ull add2(ull a, ull b) {
    ull r;
    asm("add.rn.f32x2 %0, %1, %2;" : "=l"(r) : "l"(a), "l"(b));
    return r;
}

// dtype probe: for int64 values < 2^31 every odd 32-bit word is 0.
__device__ __forceinline__ int probe_is64(const void* ei) {
    const int* w = (const int*)ei;
    int z = 0;
#pragma unroll
    for (int t = 1; t < 64; t += 2) z |= w[t];
    return (z == 0) ? 1 : 0;
}

// ---------------------------------------------------------------- histogram (4 edges/thread)
__global__ void k_hist(const void* __restrict__ ei, int E) {
    __shared__ int s_is64;
    if (threadIdx.x == 0) s_is64 = probe_is64(ei);
    __syncthreads();
    int e = 4 * (blockIdx.x * blockDim.x + threadIdx.x);
    if (e >= E) return;
    int cnt = min(4, E - e);
    int d0, d1, d2i, d3;
    if (s_is64) {
        const longlong2* d2 = (const longlong2*)((const long long*)ei + E);
        longlong2 a = d2[e >> 1];
        d0 = (int)a.x; d1 = (int)a.y;
        longlong2 b = (cnt > 2) ? d2[(e >> 1) + 1] : a;
        d2i = (int)b.x; d3 = (int)b.y;
    } else {
        int4 a = ((const int4*)((const int*)ei + E))[e >> 2];
        d0 = a.x; d1 = a.y; d2i = a.z; d3 = a.w;
    }
    atomicAdd(&g_deg[d0], 1);
    if (cnt > 1) atomicAdd(&g_deg[d1], 1);
    if (cnt > 2) atomicAdd(&g_deg[d2i], 1);
    if (cnt > 3) atomicAdd(&g_deg[d3], 1);
}

// ---------------------------------------------------------------- 3-phase scan
__device__ __forceinline__ int warp_iscan(int v, int lane) {
#pragma unroll
    for (int o = 1; o < 32; o <<= 1) {
        int t = __shfl_up_sync(0xFFFFFFFFu, v, o);
        if (lane >= o) v += t;
    }
    return v;
}

__global__ void k_scanA(int N) {
    int idx = blockIdx.x * SCAN_B + threadIdx.x;
    int v = (idx < N) ? g_deg[idx] : 0;
    int lane = threadIdx.x & 31, wid = threadIdx.x >> 5;
#pragma unroll
    for (int o = 16; o > 0; o >>= 1) v += __shfl_down_sync(0xFFFFFFFFu, v, o);
    __shared__ int ws[SCAN_B / 32];
    if (lane == 0) ws[wid] = v;
    __syncthreads();
    if (threadIdx.x < SCAN_B / 32) {
        int t = ws[threadIdx.x];
#pragma unroll
        for (int o = 8; o > 0; o >>= 1) t += __shfl_down_sync(0xFFFFu, t, o);
        if (threadIdx.x == 0) g_part[blockIdx.x] = t;
    }
}

__global__ void k_scanB(int nblk) {
    int t = threadIdx.x, lane = t & 31, wid = t >> 5;
    int v = (t < nblk) ? g_part[t] : 0;
    int s = warp_iscan(v, lane);
    __shared__ int ws[4];
    if (lane == 31) ws[wid] = s;
    __syncthreads();
    int add = 0;
    for (int k = 0; k < wid; k++) add += ws[k];
    if (t < nblk) g_part[t] = s - v + add;  // exclusive
}

__global__ void k_scanC(int N) {
    int idx = blockIdx.x * SCAN_B + threadIdx.x;
    int v = (idx < N) ? g_deg[idx] : 0;
    int lane = threadIdx.x & 31, wid = threadIdx.x >> 5;
    int s = warp_iscan(v, lane);
    __shared__ int ws[SCAN_B / 32];
    if (lane == 31) ws[wid] = s;
    __syncthreads();
    if (threadIdx.x < 32) {
        int t = (threadIdx.x < SCAN_B / 32) ? ws[threadIdx.x] : 0;
        t = warp_iscan(t, threadIdx.x);
        if (threadIdx.x < SCAN_B / 32) ws[threadIdx.x] = t;
    }
    __syncthreads();
    int wexcl = (wid > 0) ? ws[wid - 1] : 0;
    int off = g_part[blockIdx.x] + wexcl + (s - v);
    if (idx < N) {
        g_rowdeg[idx] = make_int2(off, v);
        g_cursor[idx] = off;
        g_deg[idx] = 0;   // reset for next graph replay
    }
}

// ---------------------------------------------------------------- scatter (4 edges/thread)
__global__ void k_scatter(const void* __restrict__ ei, int E) {
    __shared__ int s_is64;
    if (threadIdx.x == 0) s_is64 = probe_is64(ei);
    __syncthreads();
    int e = 4 * (blockIdx.x * blockDim.x + threadIdx.x);
    if (e >= E) return;
    int cnt = min(4, E - e);
    int s0, s1, s2v, s3, d0, d1, d2v, d3;
    if (s_is64) {
        const longlong2* s2 = (const longlong2*)ei;
        const longlong2* d2 = (const longlong2*)((const long long*)ei + E);
        longlong2 sa = s2[e >> 1], da = d2[e >> 1];
        s0 = (int)sa.x; s1 = (int)sa.y; d0 = (int)da.x; d1 = (int)da.y;
        longlong2 sb = (cnt > 2) ? s2[(e >> 1) + 1] : sa;
        longlong2 db = (cnt > 2) ? d2[(e >> 1) + 1] : da;
        s2v = (int)sb.x; s3 = (int)sb.y; d2v = (int)db.x; d3 = (int)db.y;
    } else {
        int4 sa = ((const int4*)ei)[e >> 2];
        int4 da = ((const int4*)((const int*)ei + E))[e >> 2];
        s0 = sa.x; s1 = sa.y; s2v = sa.z; s3 = sa.w;
        d0 = da.x; d1 = da.y; d2v = da.z; d3 = da.w;
    }
    int p = atomicAdd(&g_cursor[d0], 1);
    g_src_s[p] = s0;
    if (cnt > 1) { p = atomicAdd(&g_cursor[d1], 1); g_src_s[p] = s1; }
    if (cnt > 2) { p = atomicAdd(&g_cursor[d2v], 1); g_src_s[p] = s2v; }
    if (cnt > 3) { p = atomicAdd(&g_cursor[d3], 1); g_src_s[p] = s3; }
}

// ---------------------------------------------------------------- P,Q node transforms
// warp per 4 nodes per iteration; lane owns output pair (2*lane, 2*lane+1).
__global__ void k_pq(const float* __restrict__ x, const float* __restrict__ W1,
                     const float* __restrict__ b1, int N) {
    __shared__ ull A2[64 * 32];  // [d][pair] : (W1a-W1b)^T, k-pairs packed
    __shared__ ull B2[64 * 32];  // [d][pair] : W1b^T
    int tid = threadIdx.x;
    for (int idx = tid; idx < 2048; idx += blockDim.x) {
        int d = idx >> 5, pp = idx & 31;
        int k0 = 2 * pp, k1 = 2 * pp + 1;
        float w0a = W1[k0 * 128 + d], w0b = W1[k0 * 128 + 64 + d];
        float w1a = W1[k1 * 128 + d], w1b = W1[k1 * 128 + 64 + d];
        A2[idx] = pack2(w0a - w0b, w1a - w1b);
        B2[idx] = pack2(w0b, w1b);
    }
    __syncthreads();
    int lane = tid & 31;
    int warps = (gridDim.x * blockDim.x) >> 5;
    int gw = (blockIdx.x * blockDim.x + tid) >> 5;
    ull* P2 = (ull*)g_P;
    ull* Q2 = (ull*)g_Q;
    ull bias = pack2(b1[2 * lane], b1[2 * lane + 1]);
    int Nlast = N - 1;
    for (int g = gw; g * 4 < N; g += warps) {
        int n0 = min(4 * g + 0, Nlast), n1 = min(4 * g + 1, Nlast);
        int n2 = min(4 * g + 2, Nlast), n3 = min(4 * g + 3, Nlast);
        const float4* x0 = (const float4*)(x + (size_t)n0 * 64);
        const float4* x1 = (const float4*)(x + (size_t)n1 * 64);
        const float4* x2 = (const float4*)(x + (size_t)n2 * 64);
        const float4* x3 = (const float4*)(x + (size_t)n3 * 64);
        ull p0 = bias, p1 = bias, p2 = bias, p3 = bias;
        ull q0 = 0, q1 = 0, q2 = 0, q3 = 0;
#pragma unroll
        for (int t = 0; t < 16; t++) {
            float4 a0 = __ldg(&x0[t]), a1 = __ldg(&x1[t]);
            float4 a2 = __ldg(&x2[t]), a3 = __ldg(&x3[t]);
#pragma unroll
            for (int u = 0; u < 4; u++) {
                int d = 4 * t + u;
                ull wA = A2[d * 32 + lane], wB = B2[d * 32 + lane];
                float v0 = (u == 0) ? a0.x : (u == 1) ? a0.y : (u == 2) ? a0.z : a0.w;
                float v1 = (u == 0) ? a1.x : (u == 1) ? a1.y : (u == 2) ? a1.z : a1.w;
                float v2 = (u == 0) ? a2.x : (u == 1) ? a2.y : (u == 2) ? a2.z : a2.w;
                float v3 = (u == 0) ? a3.x : (u == 1) ? a3.y : (u == 2) ? a3.z : a3.w;
                ull e0 = pack2(v0, v0), e1 = pack2(v1, v1);
                ull e2 = pack2(v2, v2), e3 = pack2(v3, v3);
                fma2(p0, e0, wA); fma2(q0, e0, wB);
                fma2(p1, e1, wA); fma2(q1, e1, wB);
                fma2(p2, e2, wA); fma2(q2, e2, wB);
                fma2(p3, e3, wA); fma2(q3, e3, wB);
            }
        }
        P2[(size_t)n0 * 32 + lane] = p0; Q2[(size_t)n0 * 32 + lane] = q0;
        P2[(size_t)n1 * 32 + lane] = p1; Q2[(size_t)n1 * 32 + lane] = q1;
        P2[(size_t)n2 * 32 + lane] = p2; Q2[(size_t)n2 * 32 + lane] = q2;
        P2[(size_t)n3 * 32 + lane] = p3; Q2[(size_t)n3 * 32 + lane] = q3;
    }
}

// ---------------------------------------------------------------- main edge kernel
// block-per-node (128 threads). t = tid&63 owns W2 row t (32 ull regs).
// half = tid>>6: half 0 processes even edges, half 1 odd edges of each pair.
// h staged in smem [buf][half][64], broadcast LDS.128 reads, 1 sync per pair.
__global__ void __launch_bounds__(128, 4) k_edge(
    const float* __restrict__ b2, const float* __restrict__ W2,
    float* __restrict__ out, int N, int E)
{
    __shared__ __align__(16) float h_s[2][2][64];   // [buf][half][dim]
    __shared__ float rsh[64];

    int tid = threadIdx.x;
    int t = tid & 63;
    int half = tid >> 6;

    // W2 row t as 32 d-pairs (register-resident)
    ull w[32];
    const ull* wr = (const ull*)(W2 + t * 64);
#pragma unroll
    for (int j = 0; j < 32; j++) w[j] = __ldg(&wr[j]);
    float b2v = b2[t];

    int buf = 0;

    for (int i = blockIdx.x; i < N; i += gridDim.x) {
        int2 rd = g_rowdeg[i];          // block-uniform
        int row = rd.x, deg = rd.y;
        if (deg == 0) {
            if (half == 0) out[(size_t)i * 64 + t] = 0.f;
            continue;                    // uniform: no barrier divergence
        }
        int last = deg - 1;
        float p = g_P[(size_t)i * 64 + t];
        float rm = -CUDART_INF_F;

        // prefetch first edge of this half
        int j0 = g_src_s[row + min(half, last)];
        float q = g_Q[(size_t)j0 * 64 + t];

        for (int e = 0; e < deg; e += 2) {
            // prefetch next pair's q for this half (clamped; dups benign for max)
            int jn = g_src_s[row + min(e + 2 + half, last)];
            float qn = g_Q[(size_t)jn * 64 + t];

            float h = p + q;
            h = fmaxf(h, 0.01f * h);
            h_s[buf][half][t] = h;
            __syncthreads();

            // GEMV row t of this half's edge: 32 fma2, broadcast LDS.128
            const ulonglong2* hq = (const ulonglong2*)h_s[buf][half];
            ull a0 = 0ull, a1 = 0ull;
#pragma unroll
            for (int m = 0; m < 16; m++) {
                ulonglong2 u = hq[m];    // dims 4m..4m+3
                fma2(a0, u.x, w[2 * m]);
                fma2(a1, u.y, w[2 * m + 1]);
            }
            a0 = add2(a0, a1);
            float lo, hi;
            unpack2(a0, lo, hi);
            rm = fmaxf(rm, lo + hi);

            q = qn;
            buf ^= 1;
        }

        // combine halves (half1 -> smem; half0 reduces and writes)
        if (half == 1) rsh[t] = rm;
        __syncthreads();
        if (half == 0)
            out[(size_t)i * 64 + t] = tanhf(fmaxf(rm, rsh[t]) + b2v);
        // next node's first edge-loop __syncthreads orders rsh reuse
    }
}

// ---------------------------------------------------------------- launch
extern "C" void kernel_launch(void* const* d_in, const int* in_sizes, int n_in,
                              void* d_out, int out_size) {
    const float* x  = (const float*)d_in[0];
    const void*  ei = d_in[1];
    const float* W1 = (const float*)d_in[2];
    const float* b1 = (const float*)d_in[3];
    const float* W2 = (const float*)d_in[4];
    const float* b2 = (const float*)d_in[5];
    int N = in_sizes[0] / 64;
    int E = in_sizes[1] / 2;
    float* out = (float*)d_out;
    int nblk = (N + SCAN_B - 1) / SCAN_B;

    k_hist<<<(E / 4 + 255) / 256, 256>>>(ei, E);
    k_scanA<<<nblk, SCAN_B>>>(N);
    k_scanB<<<1, 128>>>(nblk);
    k_scanC<<<nblk, SCAN_B>>>(N);
    k_scatter<<<(E / 4 + 255) / 256, 256>>>(ei, E);
    k_pq<<<296, 256>>>(x, W1, b1, N);
    k_edge<<<N, 128>>>(b2, W2, out, N, E);
}

// round 11
// speedup vs baseline: 3.2202x; 3.2202x over previous
#include <cuda_runtime.h>
#include <math_constants.h>

// Breadth_45896020525813 — fused GNN layer (round 10):
//   P = x @ (W1a - W1b)^T + b1 ; Q = x @ W1b^T     (node-level)
//   per edge: h = leaky(P[dst]+Q[src]); msg = h@W2^T ; max over edges per dst
//   out = tanh(max + b2), empty rows -> 0
//
// k_edge: warp-pair per node. Each warp independent (no cross-warp sync):
// role r warp owns W2 rows r*32+lane (32 ull regs), computes h redundantly,
// K-packed f32x2 GEMV, 2 edges/iter, 1 syncwarp/pair. ~110 regs -> 16 warps/SM.

typedef unsigned long long ull;

#define NMAX 50000
#define EMAX 800000
#define SCAN_B 512

__device__ float g_P[NMAX * 64];   // P + b1, pair-packed [n][32] ull view
__device__ float g_Q[NMAX * 64];
__device__ int   g_src_s[EMAX];    // src ids grouped by dst
__device__ int   g_deg[NMAX];      // zero at load; re-zeroed in k_scanC
__device__ int2  g_rowdeg[NMAX];   // {row start, degree}
__device__ int   g_cursor[NMAX];
__device__ int   g_part[128];

__device__ __forceinline__ ull pack2(float lo, float hi) {
    ull r;
    asm("mov.b64 %0, {%1, %2};" : "=l"(r) : "f"(lo), "f"(hi));
    return r;
}
__device__ __forceinline__ void unpack2(ull v, float& lo, float& hi) {
    asm("mov.b64 {%0, %1}, %2;" : "=f"(lo), "=f"(hi) : "l"(v));
}
__device__ __forceinline__ void fma2(ull& acc, ull a, ull b) {
    asm("fma.rn.f32x2 %0, %1, %2, %0;" : "+l"(acc) : "l"(a), "l"(b));
}
__device__ __forceinline__ ull add2(ull a, ull b) {
    ull r;
    asm("add.rn.f32x2 %0, %1, %2;" : "=l"(r) : "l"(a), "l"(b));
    return r;
}

// dtype probe: for int64 values < 2^31 every odd 32-bit word is 0.
__device__ __forceinline__ int probe_is64(const void* ei) {
    const int* w = (const int*)ei;
    int z = 0;
#pragma unroll
    for (int t = 1; t < 64; t += 2) z |= w[t];
    return (z == 0) ? 1 : 0;
}

// ---------------------------------------------------------------- histogram (4 edges/thread)
__global__ void k_hist(const void* __restrict__ ei, int E) {
    __shared__ int s_is64;
    if (threadIdx.x == 0) s_is64 = probe_is64(ei);
    __syncthreads();
    int e = 4 * (blockIdx.x * blockDim.x + threadIdx.x);
    if (e >= E) return;
    int cnt = min(4, E - e);
    int d0, d1, d2i, d3;
    if (s_is64) {
        const longlong2* d2 = (const longlong2*)((const long long*)ei + E);
        longlong2 a = d2[e >> 1];
        d0 = (int)a.x; d1 = (int)a.y;
        longlong2 b = (cnt > 2) ? d2[(e >> 1) + 1] : a;
        d2i = (int)b.x; d3 = (int)b.y;
    } else {
        int4 a = ((const int4*)((const int*)ei + E))[e >> 2];
        d0 = a.x; d1 = a.y; d2i = a.z; d3 = a.w;
    }
    atomicAdd(&g_deg[d0], 1);
    if (cnt > 1) atomicAdd(&g_deg[d1], 1);
    if (cnt > 2) atomicAdd(&g_deg[d2i], 1);
    if (cnt > 3) atomicAdd(&g_deg[d3], 1);
}

// ---------------------------------------------------------------- 3-phase scan
__device__ __forceinline__ int warp_iscan(int v, int lane) {
#pragma unroll
    for (int o = 1; o < 32; o <<= 1) {
        int t = __shfl_up_sync(0xFFFFFFFFu, v, o);
        if (lane >= o) v += t;
    }
    return v;
}

__global__ void k_scanA(int N) {
    int idx = blockIdx.x * SCAN_B + threadIdx.x;
    int v = (idx < N) ? g_deg[idx] : 0;
    int lane = threadIdx.x & 31, wid = threadIdx.x >> 5;
#pragma unroll
    for (int o = 16; o > 0; o >>= 1) v += __shfl_down_sync(0xFFFFFFFFu, v, o);
    __shared__ int ws[SCAN_B / 32];
    if (lane == 0) ws[wid] = v;
    __syncthreads();
    if (threadIdx.x < SCAN_B / 32) {
        int t = ws[threadIdx.x];
#pragma unroll
        for (int o = 8; o > 0; o >>= 1) t += __shfl_down_sync(0xFFFFu, t, o);
        if (threadIdx.x == 0) g_part[blockIdx.x] = t;
    }
}

__global__ void k_scanB(int nblk) {
    int t = threadIdx.x, lane = t & 31, wid = t >> 5;
    int v = (t < nblk) ? g_part[t] : 0;
    int s = warp_iscan(v, lane);
    __shared__ int ws[4];
    if (lane == 31) ws[wid] = s;
    __syncthreads();
    int add = 0;
    for (int k = 0; k < wid; k++) add += ws[k];
    if (t < nblk) g_part[t] = s - v + add;  // exclusive
}

__global__ void k_scanC(int N) {
    int idx = blockIdx.x * SCAN_B + threadIdx.x;
    int v = (idx < N) ? g_deg[idx] : 0;
    int lane = threadIdx.x & 31, wid = threadIdx.x >> 5;
    int s = warp_iscan(v, lane);
    __shared__ int ws[SCAN_B / 32];
    if (lane == 31) ws[wid] = s;
    __syncthreads();
    if (threadIdx.x < 32) {
        int t = (threadIdx.x < SCAN_B / 32) ? ws[threadIdx.x] : 0;
        t = warp_iscan(t, threadIdx.x);
        if (threadIdx.x < SCAN_B / 32) ws[threadIdx.x] = t;
    }
    __syncthreads();
    int wexcl = (wid > 0) ? ws[wid - 1] : 0;
    int off = g_part[blockIdx.x] + wexcl + (s - v);
    if (idx < N) {
        g_rowdeg[idx] = make_int2(off, v);
        g_cursor[idx] = off;
        g_deg[idx] = 0;   // reset for next graph replay
    }
}

// ---------------------------------------------------------------- scatter (4 edges/thread)
__global__ void k_scatter(const void* __restrict__ ei, int E) {
    __shared__ int s_is64;
    if (threadIdx.x == 0) s_is64 = probe_is64(ei);
    __syncthreads();
    int e = 4 * (blockIdx.x * blockDim.x + threadIdx.x);
    if (e >= E) return;
    int cnt = min(4, E - e);
    int s0, s1, s2v, s3, d0, d1, d2v, d3;
    if (s_is64) {
        const longlong2* s2 = (const longlong2*)ei;
        const longlong2* d2 = (const longlong2*)((const long long*)ei + E);
        longlong2 sa = s2[e >> 1], da = d2[e >> 1];
        s0 = (int)sa.x; s1 = (int)sa.y; d0 = (int)da.x; d1 = (int)da.y;
        longlong2 sb = (cnt > 2) ? s2[(e >> 1) + 1] : sa;
        longlong2 db = (cnt > 2) ? d2[(e >> 1) + 1] : da;
        s2v = (int)sb.x; s3 = (int)sb.y; d2v = (int)db.x; d3 = (int)db.y;
    } else {
        int4 sa = ((const int4*)ei)[e >> 2];
        int4 da = ((const int4*)((const int*)ei + E))[e >> 2];
        s0 = sa.x; s1 = sa.y; s2v = sa.z; s3 = sa.w;
        d0 = da.x; d1 = da.y; d2v = da.z; d3 = da.w;
    }
    int p = atomicAdd(&g_cursor[d0], 1);
    g_src_s[p] = s0;
    if (cnt > 1) { p = atomicAdd(&g_cursor[d1], 1); g_src_s[p] = s1; }
    if (cnt > 2) { p = atomicAdd(&g_cursor[d2v], 1); g_src_s[p] = s2v; }
    if (cnt > 3) { p = atomicAdd(&g_cursor[d3], 1); g_src_s[p] = s3; }
}

// ---------------------------------------------------------------- P,Q node transforms
// warp per 4 nodes per iteration; lane owns output pair (2*lane, 2*lane+1).
__global__ void k_pq(const float* __restrict__ x, const float* __restrict__ W1,
                     const float* __restrict__ b1, int N) {
    __shared__ ull A2[64 * 32];  // [d][pair] : (W1a-W1b)^T, k-pairs packed
    __shared__ ull B2[64 * 32];  // [d][pair] : W1b^T
    int tid = threadIdx.x;
    for (int idx = tid; idx < 2048; idx += blockDim.x) {
        int d = idx >> 5, pp = idx & 31;
        int k0 = 2 * pp, k1 = 2 * pp + 1;
        float w0a = W1[k0 * 128 + d], w0b = W1[k0 * 128 + 64 + d];
        float w1a = W1[k1 * 128 + d], w1b = W1[k1 * 128 + 64 + d];
        A2[idx] = pack2(w0a - w0b, w1a - w1b);
        B2[idx] = pack2(w0b, w1b);
    }
    __syncthreads();
    int lane = tid & 31;
    int warps = (gridDim.x * blockDim.x) >> 5;
    int gw = (blockIdx.x * blockDim.x + tid) >> 5;
    ull* P2 = (ull*)g_P;
    ull* Q2 = (ull*)g_Q;
    ull bias = pack2(b1[2 * lane], b1[2 * lane + 1]);
    int Nlast = N - 1;
    for (int g = gw; g * 4 < N; g += warps) {
        int n0 = min(4 * g + 0, Nlast), n1 = min(4 * g + 1, Nlast);
        int n2 = min(4 * g + 2, Nlast), n3 = min(4 * g + 3, Nlast);
        const float4* x0 = (const float4*)(x + (size_t)n0 * 64);
        const float4* x1 = (const float4*)(x + (size_t)n1 * 64);
        const float4* x2 = (const float4*)(x + (size_t)n2 * 64);
        const float4* x3 = (const float4*)(x + (size_t)n3 * 64);
        ull p0 = bias, p1 = bias, p2 = bias, p3 = bias;
        ull q0 = 0, q1 = 0, q2 = 0, q3 = 0;
#pragma unroll
        for (int t = 0; t < 16; t++) {
            float4 a0 = __ldg(&x0[t]), a1 = __ldg(&x1[t]);
            float4 a2 = __ldg(&x2[t]), a3 = __ldg(&x3[t]);
#pragma unroll
            for (int u = 0; u < 4; u++) {
                int d = 4 * t + u;
                ull wA = A2[d * 32 + lane], wB = B2[d * 32 + lane];
                float v0 = (u == 0) ? a0.x : (u == 1) ? a0.y : (u == 2) ? a0.z : a0.w;
                float v1 = (u == 0) ? a1.x : (u == 1) ? a1.y : (u == 2) ? a1.z : a1.w;
                float v2 = (u == 0) ? a2.x : (u == 1) ? a2.y : (u == 2) ? a2.z : a2.w;
                float v3 = (u == 0) ? a3.x : (u == 1) ? a3.y : (u == 2) ? a3.z : a3.w;
                ull e0 = pack2(v0, v0), e1 = pack2(v1, v1);
                ull e2 = pack2(v2, v2), e3 = pack2(v3, v3);
                fma2(p0, e0, wA); fma2(q0, e0, wB);
                fma2(p1, e1, wA); fma2(q1, e1, wB);
                fma2(p2, e2, wA); fma2(q2, e2, wB);
                fma2(p3, e3, wA); fma2(q3, e3, wB);
            }
        }
        P2[(size_t)n0 * 32 + lane] = p0; Q2[(size_t)n0 * 32 + lane] = q0;
        P2[(size_t)n1 * 32 + lane] = p1; Q2[(size_t)n1 * 32 + lane] = q1;
        P2[(size_t)n2 * 32 + lane] = p2; Q2[(size_t)n2 * 32 + lane] = q2;
        P2[(size_t)n3 * 32 + lane] = p3; Q2[(size_t)n3 * 32 + lane] = q3;
    }
}

// ---------------------------------------------------------------- main edge kernel
// Warp-pair per node: global warp gw -> node gw/2, role gw&1.
// Lane owns W2 row (role*32 + lane) as 32 d-pair ull regs. Each warp
// independently computes h (lane dims 2*lane,2*lane+1) into its own smem
// buffer; K-packed f32x2 GEMV; 2 edges/iter; 1 syncwarp/pair; no cross-warp sync.
__global__ void __launch_bounds__(256, 2) k_edge(
    const float* __restrict__ b2, const float* __restrict__ W2,
    float* __restrict__ out, int N, int E)
{
    __shared__ __align__(16) ull h_s[8][2][2][32];  // [warp][buf][edge01][32 d-pairs]
    int lane = threadIdx.x & 31;
    int wid = threadIdx.x >> 5;

    int gw = (blockIdx.x * blockDim.x + threadIdx.x) >> 5;
    int role = gw & 1;
    int node0 = gw >> 1;
    int nodestride = (gridDim.x * blockDim.x) >> 6;  // total warps / 2

    int t = role * 32 + lane;   // owned W2 row / output column
    ull w[32];
    const ull* wr = (const ull*)(W2 + t * 64);
#pragma unroll
    for (int j = 0; j < 32; j++) w[j] = __ldg(&wr[j]);
    float b2v = b2[t];

    const ull* P2 = (const ull*)g_P;
    const ull* Q2 = (const ull*)g_Q;

    for (int i = node0; i < N; i += nodestride) {
        int2 rd = g_rowdeg[i];
        int row = rd.x, deg = rd.y;
        float* orow = out + (size_t)i * 64;
        if (deg == 0) {
            orow[t] = 0.f;
            continue;
        }
        int last = deg - 1;
        ull pb = P2[(size_t)i * 32 + lane];

        int j0 = g_src_s[row];
        int j1 = g_src_s[row + min(1, last)];
        ull q0 = Q2[(size_t)j0 * 32 + lane];
        ull q1 = Q2[(size_t)j1 * 32 + lane];
        int j2 = g_src_s[row + min(2, last)];
        int j3 = g_src_s[row + min(3, last)];

        float rm = -CUDART_INF_F;
        int buf = 0;

        for (int e = 0; e < deg; e += 2) {
            // src prefetch: 2 pairs ahead (warp-uniform branch)
            int j4, j5;
            if (e + 5 < deg) {
                j4 = g_src_s[row + e + 4];
                j5 = g_src_s[row + e + 5];
            } else {
                j4 = g_src_s[row + min(e + 4, last)];
                j5 = j4;
            }
            // Q prefetch: 1 pair ahead
            ull qp0 = Q2[(size_t)j2 * 32 + lane];
            ull qp1 = Q2[(size_t)j3 * 32 + lane];

            // h for both edges: lane owns dims (2*lane, 2*lane+1)
            ull* h0w = h_s[wid][buf][0];
            ull* h1w = h_s[wid][buf][1];
            {
                ull s = add2(pb, q0);
                float lo, hi;
                unpack2(s, lo, hi);
                lo = fmaxf(lo, 0.01f * lo);
                hi = fmaxf(hi, 0.01f * hi);
                h0w[lane] = pack2(lo, hi);
            }
            {
                ull s = add2(pb, q1);
                float lo, hi;
                unpack2(s, lo, hi);
                lo = fmaxf(lo, 0.01f * lo);
                hi = fmaxf(hi, 0.01f * hi);
                h1w[lane] = pack2(lo, hi);
            }
            __syncwarp();   // separates read(buf, iter-2) from store(buf, iter)

            // K-packed GEMV for owned row, both edges (4 chains)
            const ulonglong2* h0q = (const ulonglong2*)h0w;
            const ulonglong2* h1q = (const ulonglong2*)h1w;
            ull a00 = 0, a01 = 0, a10 = 0, a11 = 0;
#pragma unroll
            for (int m = 0; m < 16; m++) {
                ulonglong2 u0 = h0q[m];   // d-pairs 2m, 2m+1
                ulonglong2 u1 = h1q[m];
                fma2(a00, u0.x, w[2 * m]);
                fma2(a01, u0.y, w[2 * m + 1]);
                fma2(a10, u1.x, w[2 * m]);
                fma2(a11, u1.y, w[2 * m + 1]);
            }
            a00 = add2(a00, a01);
            a10 = add2(a10, a11);
            float lo, hi;
            unpack2(a00, lo, hi);
            rm = fmaxf(rm, lo + hi);
            unpack2(a10, lo, hi);
            rm = fmaxf(rm, lo + hi);

            q0 = qp0; q1 = qp1;
            j2 = j4;  j3 = j5;
            buf ^= 1;
        }
        orow[t] = tanhf(rm + b2v);
    }
}

// ---------------------------------------------------------------- launch
extern "C" void kernel_launch(void* const* d_in, const int* in_sizes, int n_in,
                              void* d_out, int out_size) {
    const float* x  = (const float*)d_in[0];
    const void*  ei = d_in[1];
    const float* W1 = (const float*)d_in[2];
    const float* b1 = (const float*)d_in[3];
    const float* W2 = (const float*)d_in[4];
    const float* b2 = (const float*)d_in[5];
    int N = in_sizes[0] / 64;
    int E = in_sizes[1] / 2;
    float* out = (float*)d_out;
    int nblk = (N + SCAN_B - 1) / SCAN_B;

    k_hist<<<(E / 4 + 255) / 256, 256>>>(ei, E);
    k_scanA<<<nblk, SCAN_B>>>(N);
    k_scanB<<<1, 128>>>(nblk);
    k_scanC<<<nblk, SCAN_B>>>(N);
    k_scatter<<<(E / 4 + 255) / 256, 256>>>(ei, E);
    k_pq<<<296, 256>>>(x, W1, b1, N);
    k_edge<<<296, 256>>>(b2, W2, out, N, E);
}

// round 12
// speedup vs baseline: 3.5601x; 1.1056x over previous
#include <cuda_runtime.h>
#include <math_constants.h>

// Breadth_45896020525813 — fused GNN layer (round 12):
//   P = x @ (W1a - W1b)^T + b1 ; Q = x @ W1b^T     (node-level)
//   per edge: h = leaky(P[dst]+Q[src]); msg = h@W2^T ; max over edges per dst
//   out = tanh(max + b2), empty rows -> 0
//
// k_edge: round-8 layout (warp-per-node, lane owns 2 W2 rows, K-packed f32x2
// GEMV) but 4 edges per iteration: 16 independent acc chains, 1 syncwarp per
// 4 edges, Q prefetched a full iteration ahead. Same total work, more ILP.

typedef unsigned long long ull;

#define NMAX 50000
#define EMAX 800000
#define SCAN_B 512

__device__ float g_P[NMAX * 64];   // P + b1, pair-packed [n][32] ull view
__device__ float g_Q[NMAX * 64];
__device__ int   g_src_s[EMAX];    // src ids grouped by dst
__device__ int   g_deg[NMAX];      // zero at load; re-zeroed in k_scanC
__device__ int2  g_rowdeg[NMAX];   // {row start, degree}
__device__ int   g_cursor[NMAX];
__device__ int   g_part[128];

__device__ __forceinline__ ull pack2(float lo, float hi) {
    ull r;
    asm("mov.b64 %0, {%1, %2};" : "=l"(r) : "f"(lo), "f"(hi));
    return r;
}
__device__ __forceinline__ void unpack2(ull v, float& lo, float& hi) {
    asm("mov.b64 {%0, %1}, %2;" : "=f"(lo), "=f"(hi) : "l"(v));
}
__device__ __forceinline__ void fma2(ull& acc, ull a, ull b) {
    asm("fma.rn.f32x2 %0, %1, %2, %0;" : "+l"(acc) : "l"(a), "l"(b));
}
__device__ __forceinline__ ull add2(ull a, ull b) {
    ull r;
    asm("add.rn.f32x2 %0, %1, %2;" : "=l"(r) : "l"(a), "l"(b));
    return r;
}

// dtype probe: for int64 values < 2^31 every odd 32-bit word is 0.
__device__ __forceinline__ int probe_is64(const void* ei) {
    const int* w = (const int*)ei;
    int z = 0;
#pragma unroll
    for (int t = 1; t < 64; t += 2) z |= w[t];
    return (z == 0) ? 1 : 0;
}

// ---------------------------------------------------------------- histogram (4 edges/thread)
__global__ void k_hist(const void* __restrict__ ei, int E) {
    __shared__ int s_is64;
    if (threadIdx.x == 0) s_is64 = probe_is64(ei);
    __syncthreads();
    int e = 4 * (blockIdx.x * blockDim.x + threadIdx.x);
    if (e >= E) return;
    int cnt = min(4, E - e);
    int d0, d1, d2i, d3;
    if (s_is64) {
        const longlong2* d2 = (const longlong2*)((const long long*)ei + E);
        longlong2 a = d2[e >> 1];
        d0 = (int)a.x; d1 = (int)a.y;
        longlong2 b = (cnt > 2) ? d2[(e >> 1) + 1] : a;
        d2i = (int)b.x; d3 = (int)b.y;
    } else {
        int4 a = ((const int4*)((const int*)ei + E))[e >> 2];
        d0 = a.x; d1 = a.y; d2i = a.z; d3 = a.w;
    }
    atomicAdd(&g_deg[d0], 1);
    if (cnt > 1) atomicAdd(&g_deg[d1], 1);
    if (cnt > 2) atomicAdd(&g_deg[d2i], 1);
    if (cnt > 3) atomicAdd(&g_deg[d3], 1);
}

// ---------------------------------------------------------------- 3-phase scan
__device__ __forceinline__ int warp_iscan(int v, int lane) {
#pragma unroll
    for (int o = 1; o < 32; o <<= 1) {
        int t = __shfl_up_sync(0xFFFFFFFFu, v, o);
        if (lane >= o) v += t;
    }
    return v;
}

__global__ void k_scanA(int N) {
    int idx = blockIdx.x * SCAN_B + threadIdx.x;
    int v = (idx < N) ? g_deg[idx] : 0;
    int lane = threadIdx.x & 31, wid = threadIdx.x >> 5;
#pragma unroll
    for (int o = 16; o > 0; o >>= 1) v += __shfl_down_sync(0xFFFFFFFFu, v, o);
    __shared__ int ws[SCAN_B / 32];
    if (lane == 0) ws[wid] = v;
    __syncthreads();
    if (threadIdx.x < SCAN_B / 32) {
        int t = ws[threadIdx.x];
#pragma unroll
        for (int o = 8; o > 0; o >>= 1) t += __shfl_down_sync(0xFFFFu, t, o);
        if (threadIdx.x == 0) g_part[blockIdx.x] = t;
    }
}

__global__ void k_scanB(int nblk) {
    int t = threadIdx.x, lane = t & 31, wid = t >> 5;
    int v = (t < nblk) ? g_part[t] : 0;
    int s = warp_iscan(v, lane);
    __shared__ int ws[4];
    if (lane == 31) ws[wid] = s;
    __syncthreads();
    int add = 0;
    for (int k = 0; k < wid; k++) add += ws[k];
    if (t < nblk) g_part[t] = s - v + add;  // exclusive
}

__global__ void k_scanC(int N) {
    int idx = blockIdx.x * SCAN_B + threadIdx.x;
    int v = (idx < N) ? g_deg[idx] : 0;
    int lane = threadIdx.x & 31, wid = threadIdx.x >> 5;
    int s = warp_iscan(v, lane);
    __shared__ int ws[SCAN_B / 32];
    if (lane == 31) ws[wid] = s;
    __syncthreads();
    if (threadIdx.x < 32) {
        int t = (threadIdx.x < SCAN_B / 32) ? ws[threadIdx.x] : 0;
        t = warp_iscan(t, threadIdx.x);
        if (threadIdx.x < SCAN_B / 32) ws[threadIdx.x] = t;
    }
    __syncthreads();
    int wexcl = (wid > 0) ? ws[wid - 1] : 0;
    int off = g_part[blockIdx.x] + wexcl + (s - v);
    if (idx < N) {
        g_rowdeg[idx] = make_int2(off, v);
        g_cursor[idx] = off;
        g_deg[idx] = 0;   // reset for next graph replay
    }
}

// ---------------------------------------------------------------- scatter (4 edges/thread)
__global__ void k_scatter(const void* __restrict__ ei, int E) {
    __shared__ int s_is64;
    if (threadIdx.x == 0) s_is64 = probe_is64(ei);
    __syncthreads();
    int e = 4 * (blockIdx.x * blockDim.x + threadIdx.x);
    if (e >= E) return;
    int cnt = min(4, E - e);
    int s0, s1, s2v, s3, d0, d1, d2v, d3;
    if (s_is64) {
        const longlong2* s2 = (const longlong2*)ei;
        const longlong2* d2 = (const longlong2*)((const long long*)ei + E);
        longlong2 sa = s2[e >> 1], da = d2[e >> 1];
        s0 = (int)sa.x; s1 = (int)sa.y; d0 = (int)da.x; d1 = (int)da.y;
        longlong2 sb = (cnt > 2) ? s2[(e >> 1) + 1] : sa;
        longlong2 db = (cnt > 2) ? d2[(e >> 1) + 1] : da;
        s2v = (int)sb.x; s3 = (int)sb.y; d2v = (int)db.x; d3 = (int)db.y;
    } else {
        int4 sa = ((const int4*)ei)[e >> 2];
        int4 da = ((const int4*)((const int*)ei + E))[e >> 2];
        s0 = sa.x; s1 = sa.y; s2v = sa.z; s3 = sa.w;
        d0 = da.x; d1 = da.y; d2v = da.z; d3 = da.w;
    }
    int p = atomicAdd(&g_cursor[d0], 1);
    g_src_s[p] = s0;
    if (cnt > 1) { p = atomicAdd(&g_cursor[d1], 1); g_src_s[p] = s1; }
    if (cnt > 2) { p = atomicAdd(&g_cursor[d2v], 1); g_src_s[p] = s2v; }
    if (cnt > 3) { p = atomicAdd(&g_cursor[d3], 1); g_src_s[p] = s3; }
}

// ---------------------------------------------------------------- P,Q node transforms
__global__ void k_pq(const float* __restrict__ x, const float* __restrict__ W1,
                     const float* __restrict__ b1, int N) {
    __shared__ ull A2[64 * 32];  // [d][pair] : (W1a-W1b)^T, k-pairs packed
    __shared__ ull B2[64 * 32];  // [d][pair] : W1b^T
    int tid = threadIdx.x;
    for (int idx = tid; idx < 2048; idx += blockDim.x) {
        int d = idx >> 5, pp = idx & 31;
        int k0 = 2 * pp, k1 = 2 * pp + 1;
        float w0a = W1[k0 * 128 + d], w0b = W1[k0 * 128 + 64 + d];
        float w1a = W1[k1 * 128 + d], w1b = W1[k1 * 128 + 64 + d];
        A2[idx] = pack2(w0a - w0b, w1a - w1b);
        B2[idx] = pack2(w0b, w1b);
    }
    __syncthreads();
    int lane = tid & 31;
    int warps = (gridDim.x * blockDim.x) >> 5;
    int gw = (blockIdx.x * blockDim.x + tid) >> 5;
    ull* P2 = (ull*)g_P;
    ull* Q2 = (ull*)g_Q;
    ull bias = pack2(b1[2 * lane], b1[2 * lane + 1]);
    int Nlast = N - 1;
    for (int g = gw; g * 4 < N; g += warps) {
        int n0 = min(4 * g + 0, Nlast), n1 = min(4 * g + 1, Nlast);
        int n2 = min(4 * g + 2, Nlast), n3 = min(4 * g + 3, Nlast);
        const float4* x0 = (const float4*)(x + (size_t)n0 * 64);
        const float4* x1 = (const float4*)(x + (size_t)n1 * 64);
        const float4* x2 = (const float4*)(x + (size_t)n2 * 64);
        const float4* x3 = (const float4*)(x + (size_t)n3 * 64);
        ull p0 = bias, p1 = bias, p2 = bias, p3 = bias;
        ull q0 = 0, q1 = 0, q2 = 0, q3 = 0;
#pragma unroll
        for (int t = 0; t < 16; t++) {
            float4 a0 = __ldg(&x0[t]), a1 = __ldg(&x1[t]);
            float4 a2 = __ldg(&x2[t]), a3 = __ldg(&x3[t]);
#pragma unroll
            for (int u = 0; u < 4; u++) {
                int d = 4 * t + u;
                ull wA = A2[d * 32 + lane], wB = B2[d * 32 + lane];
                float v0 = (u == 0) ? a0.x : (u == 1) ? a0.y : (u == 2) ? a0.z : a0.w;
                float v1 = (u == 0) ? a1.x : (u == 1) ? a1.y : (u == 2) ? a1.z : a1.w;
                float v2 = (u == 0) ? a2.x : (u == 1) ? a2.y : (u == 2) ? a2.z : a2.w;
                float v3 = (u == 0) ? a3.x : (u == 1) ? a3.y : (u == 2) ? a3.z : a3.w;
                ull e0 = pack2(v0, v0), e1 = pack2(v1, v1);
                ull e2 = pack2(v2, v2), e3 = pack2(v3, v3);
                fma2(p0, e0, wA); fma2(q0, e0, wB);
                fma2(p1, e1, wA); fma2(q1, e1, wB);
                fma2(p2, e2, wA); fma2(q2, e2, wB);
                fma2(p3, e3, wA); fma2(q3, e3, wB);
            }
        }
        P2[(size_t)n0 * 32 + lane] = p0; Q2[(size_t)n0 * 32 + lane] = q0;
        P2[(size_t)n1 * 32 + lane] = p1; Q2[(size_t)n1 * 32 + lane] = q1;
        P2[(size_t)n2 * 32 + lane] = p2; Q2[(size_t)n2 * 32 + lane] = q2;
        P2[(size_t)n3 * 32 + lane] = p3; Q2[(size_t)n3 * 32 + lane] = q3;
    }
}

// ---------------------------------------------------------------- main edge kernel
// warp per dst node; lane owns W2 rows 2l,2l+1 (raw ull d-pairs, 128 regs).
// 4 edges per iteration: 16 acc chains, 1 syncwarp/4 edges, h NON-duplicated.
__global__ void __launch_bounds__(128, 2) k_edge(
    const float* __restrict__ b2, const float* __restrict__ W2,
    float* __restrict__ out, int N, int E)
{
    __shared__ __align__(16) ull h_s[4][2][4][32];  // [warp][buf][edge0..3][32 d-pairs]
    int lane = threadIdx.x & 31;
    int wid = threadIdx.x >> 5;

    int r0i = 2 * lane, r1i = 2 * lane + 1;
    ull w0[32], w1[32];
    const ull* wr0 = (const ull*)(W2 + r0i * 64);
    const ull* wr1 = (const ull*)(W2 + r1i * 64);
#pragma unroll
    for (int j = 0; j < 32; j++) { w0[j] = __ldg(&wr0[j]); w1[j] = __ldg(&wr1[j]); }
    float b2v0 = b2[r0i], b2v1 = b2[r1i];

    const ull* P2 = (const ull*)g_P;
    const ull* Q2 = (const ull*)g_Q;

    int gw = (blockIdx.x * blockDim.x + threadIdx.x) >> 5;
    int nwarps = (gridDim.x * blockDim.x) >> 5;

    for (int i = gw; i < N; i += nwarps) {
        int2 rd = g_rowdeg[i];
        int row = rd.x, deg = rd.y;
        float2* orow = (float2*)(out + (size_t)i * 64);
        if (deg == 0) {
            orow[lane] = make_float2(0.f, 0.f);
            continue;
        }
        int last = deg - 1;
        ull pb = P2[(size_t)i * 32 + lane];

        // prologue: q for edges 0..3, src for edges 4..7 (clamped; dups benign)
        int jn0 = g_src_s[row];
        int jn1 = g_src_s[row + min(1, last)];
        int jn2 = g_src_s[row + min(2, last)];
        int jn3 = g_src_s[row + min(3, last)];
        ull q0 = Q2[(size_t)jn0 * 32 + lane];
        ull q1 = Q2[(size_t)jn1 * 32 + lane];
        ull q2 = Q2[(size_t)jn2 * 32 + lane];
        ull q3 = Q2[(size_t)jn3 * 32 + lane];
        jn0 = g_src_s[row + min(4, last)];
        jn1 = g_src_s[row + min(5, last)];
        jn2 = g_src_s[row + min(6, last)];
        jn3 = g_src_s[row + min(7, last)];

        float rm0 = -CUDART_INF_F, rm1 = -CUDART_INF_F;
        int buf = 0;

        for (int e = 0; e < deg; e += 4) {
            // src for iteration after next
            int t0 = g_src_s[row + min(e + 8, last)];
            int t1 = g_src_s[row + min(e + 9, last)];
            int t2 = g_src_s[row + min(e + 10, last)];
            int t3 = g_src_s[row + min(e + 11, last)];
            // Q for next iteration (edges e+4..e+7)
            ull qp0 = Q2[(size_t)jn0 * 32 + lane];
            ull qp1 = Q2[(size_t)jn1 * 32 + lane];
            ull qp2 = Q2[(size_t)jn2 * 32 + lane];
            ull qp3 = Q2[(size_t)jn3 * 32 + lane];

            // h for 4 edges: lane owns dims (2l, 2l+1), stored once
            ull* hb = &h_s[wid][buf][0][0];
#pragma unroll
            for (int k = 0; k < 4; k++) {
                ull qq = (k == 0) ? q0 : (k == 1) ? q1 : (k == 2) ? q2 : q3;
                ull s = add2(pb, qq);
                float lo, hi;
                unpack2(s, lo, hi);
                lo = fmaxf(lo, 0.01f * lo);
                hi = fmaxf(hi, 0.01f * hi);
                hb[k * 32 + lane] = pack2(lo, hi);
            }
            __syncwarp();   // separates read(buf, iter-2) from store(buf, iter)

            const ulonglong2* h0 = (const ulonglong2*)(hb);
            const ulonglong2* h1 = (const ulonglong2*)(hb + 32);
            const ulonglong2* h2 = (const ulonglong2*)(hb + 64);
            const ulonglong2* h3 = (const ulonglong2*)(hb + 96);
            ull a00 = 0, a01 = 0, a02 = 0, a03 = 0;
            ull a10 = 0, a11 = 0, a12 = 0, a13 = 0;
            ull a20 = 0, a21 = 0, a22 = 0, a23 = 0;
            ull a30 = 0, a31 = 0, a32 = 0, a33 = 0;
#pragma unroll
            for (int m = 0; m < 16; m++) {
                ulonglong2 u0 = h0[m], u1 = h1[m], u2 = h2[m], u3 = h3[m];
                ull we = w0[2 * m], wo = w0[2 * m + 1];
                ull ve = w1[2 * m], vo = w1[2 * m + 1];
                fma2(a00, u0.x, we); fma2(a01, u0.y, wo);
                fma2(a02, u0.x, ve); fma2(a03, u0.y, vo);
                fma2(a10, u1.x, we); fma2(a11, u1.y, wo);
                fma2(a12, u1.x, ve); fma2(a13, u1.y, vo);
                fma2(a20, u2.x, we); fma2(a21, u2.y, wo);
                fma2(a22, u2.x, ve); fma2(a23, u2.y, vo);
                fma2(a30, u3.x, we); fma2(a31, u3.y, wo);
                fma2(a32, u3.x, ve); fma2(a33, u3.y, vo);
            }

            // reduce 4 edges
            float lo, hi;
            a00 = add2(a00, a01); a02 = add2(a02, a03);
            unpack2(a00, lo, hi); rm0 = fmaxf(rm0, lo + hi);
            unpack2(a02, lo, hi); rm1 = fmaxf(rm1, lo + hi);
            a10 = add2(a10, a11); a12 = add2(a12, a13);
            unpack2(a10, lo, hi); rm0 = fmaxf(rm0, lo + hi);
            unpack2(a12, lo, hi); rm1 = fmaxf(rm1, lo + hi);
            a20 = add2(a20, a21); a22 = add2(a22, a23);
            unpack2(a20, lo, hi); rm0 = fmaxf(rm0, lo + hi);
            unpack2(a22, lo, hi); rm1 = fmaxf(rm1, lo + hi);
            a30 = add2(a30, a31); a32 = add2(a32, a33);
            unpack2(a30, lo, hi); rm0 = fmaxf(rm0, lo + hi);
            unpack2(a32, lo, hi); rm1 = fmaxf(rm1, lo + hi);

            q0 = qp0; q1 = qp1; q2 = qp2; q3 = qp3;
            jn0 = t0; jn1 = t1; jn2 = t2; jn3 = t3;
            buf ^= 1;
        }
        orow[lane] = make_float2(tanhf(rm0 + b2v0), tanhf(rm1 + b2v1));
    }
}

// ---------------------------------------------------------------- launch
extern "C" void kernel_launch(void* const* d_in, const int* in_sizes, int n_in,
                              void* d_out, int out_size) {
    const float* x  = (const float*)d_in[0];
    const void*  ei = d_in[1];
    const float* W1 = (const float*)d_in[2];
    const float* b1 = (const float*)d_in[3];
    const float* W2 = (const float*)d_in[4];
    const float* b2 = (const float*)d_in[5];
    int N = in_sizes[0] / 64;
    int E = in_sizes[1] / 2;
    float* out = (float*)d_out;
    int nblk = (N + SCAN_B - 1) / SCAN_B;

    k_hist<<<(E / 4 + 255) / 256, 256>>>(ei, E);
    k_scanA<<<nblk, SCAN_B>>>(N);
    k_scanB<<<1, 128>>>(nblk);
    k_scanC<<<nblk, SCAN_B>>>(N);
    k_scatter<<<(E / 4 + 255) / 256, 256>>>(ei, E);
    k_pq<<<296, 256>>>(x, W1, b1, N);
    k_edge<<<296, 128>>>(b2, W2, out, N, E);
}